// round 1
// baseline (speedup 1.0000x reference)
#include <cuda_runtime.h>
#include <math.h>

// Problem constants (fixed shapes)
#define Bsz   4
#define Sseq  2048
#define Cin   512
#define Hn    8
#define Dh    64
#define HD    512            // Hn * Dh
#define MROWS (Bsz * Sseq)   // 8192

// Scratch buffers (allocation-free rule: __device__ globals)
__device__ float g_Q[MROWS * HD];
__device__ float g_K[MROWS * HD];
__device__ float g_V[MROWS * HD];
__device__ float g_AO[MROWS * HD];

// ---------------------------------------------------------------------------
// 128x128 tiled fp32 GEMM: C[M,N] = A[M,K] @ B[K,N], row-major.
// 256 threads, 8x8 per-thread tile, BK=8.  M,N multiples of 128; K mult of 8.
// ---------------------------------------------------------------------------
__device__ __forceinline__ void gemm128x128(const float* __restrict__ A,
                                            const float* __restrict__ Bm,
                                            float* __restrict__ C,
                                            int K, int N)
{
    __shared__ float As[8][128];   // transposed A tile: As[k][m]
    __shared__ float Bs[8][132];   // padded

    const int tid  = threadIdx.x;
    const int row0 = blockIdx.y * 128;
    const int col0 = blockIdx.x * 128;
    const int tx   = tid & 15;     // N direction
    const int ty   = tid >> 4;     // M direction

    const int arow = tid >> 1;            // 0..127
    const int acol = (tid & 1) * 4;       // 0 or 4
    const int brow = tid >> 5;            // 0..7
    const int bcol = (tid & 31) * 4;      // 0..124

    float acc[8][8];
#pragma unroll
    for (int i = 0; i < 8; i++)
#pragma unroll
        for (int j = 0; j < 8; j++) acc[i][j] = 0.f;

    const float* Aptr = A + (size_t)(row0 + arow) * K + acol;
    const float* Bptr = Bm + (size_t)brow * N + col0 + bcol;

    for (int k0 = 0; k0 < K; k0 += 8) {
        float4 av = *(const float4*)(Aptr + k0);
        float4 bv = *(const float4*)(Bptr + (size_t)k0 * N);

        As[acol + 0][arow] = av.x;
        As[acol + 1][arow] = av.y;
        As[acol + 2][arow] = av.z;
        As[acol + 3][arow] = av.w;
        *(float4*)&Bs[brow][bcol] = bv;
        __syncthreads();

#pragma unroll
        for (int kk = 0; kk < 8; kk++) {
            float a[8], b[8];
            *(float4*)&a[0] = *(const float4*)&As[kk][ty * 8];
            *(float4*)&a[4] = *(const float4*)&As[kk][ty * 8 + 4];
            *(float4*)&b[0] = *(const float4*)&Bs[kk][tx * 8];
            *(float4*)&b[4] = *(const float4*)&Bs[kk][tx * 8 + 4];
#pragma unroll
            for (int i = 0; i < 8; i++)
#pragma unroll
                for (int j = 0; j < 8; j++)
                    acc[i][j] = fmaf(a[i], b[j], acc[i][j]);
        }
        __syncthreads();
    }

#pragma unroll
    for (int i = 0; i < 8; i++) {
        float* cp = C + (size_t)(row0 + ty * 8 + i) * N + col0 + tx * 8;
        float4 o0, o1;
        o0.x = acc[i][0]; o0.y = acc[i][1]; o0.z = acc[i][2]; o0.w = acc[i][3];
        o1.x = acc[i][4]; o1.y = acc[i][5]; o1.z = acc[i][6]; o1.w = acc[i][7];
        *(float4*)cp       = o0;
        *(float4*)(cp + 4) = o1;
    }
}

// QKV projections: gridDim.z selects Wq/Wk/Wv -> g_Q/g_K/g_V
__global__ __launch_bounds__(256) void qkv_kernel(const float* __restrict__ x,
                                                  const float* __restrict__ Wq,
                                                  const float* __restrict__ Wk,
                                                  const float* __restrict__ Wv)
{
    const float* W = (blockIdx.z == 0) ? Wq : (blockIdx.z == 1) ? Wk : Wv;
    float* Cout    = (blockIdx.z == 0) ? g_Q : (blockIdx.z == 1) ? g_K : g_V;
    gemm128x128(x, W, Cout, Cin, HD);
}

// Output projection: out = g_AO @ Wx
__global__ __launch_bounds__(256) void out_kernel(const float* __restrict__ Wx,
                                                  float* __restrict__ out)
{
    gemm128x128(g_AO, Wx, out, HD, Cin);
}

// ---------------------------------------------------------------------------
// Flash-style attention. One CTA per (b, h, 64-query tile). 256 threads:
// 4 threads per query row, each owns 16 of the 64 head dims.
// Online softmax over key tiles of 64.  Keys >= length[b] masked to -1e30;
// query rows >= length[b] write zeros (matches reference masking).
// ---------------------------------------------------------------------------
__global__ __launch_bounds__(256) void attn_kernel(const int* __restrict__ length)
{
    __shared__ float Ks[64][64];
    __shared__ float Vs[64][64];

    const int b  = blockIdx.z;
    const int h  = blockIdx.y;
    const int q0 = blockIdx.x * 64;
    const int L  = length[b];

    const int tid  = threadIdx.x;
    const int qrow = tid >> 2;
    const int sub  = tid & 3;
    const int d0   = sub * 16;
    const int qg   = q0 + qrow;

    // Load this thread's Q fragment (16 dims) into registers
    const float* Qrow = g_Q + ((size_t)(b * Sseq + qg)) * HD + h * Dh + d0;
    float qreg[16];
#pragma unroll
    for (int j = 0; j < 16; j += 4)
        *(float4*)&qreg[j] = *(const float4*)(Qrow + j);

    float acc[16];
#pragma unroll
    for (int j = 0; j < 16; j++) acc[j] = 0.f;
    float m = -1e30f, l = 0.f;

    const int nt = (L + 63) >> 6;
    const float* Kbase = g_K + ((size_t)b * Sseq) * HD + h * Dh;
    const float* Vbase = g_V + ((size_t)b * Sseq) * HD + h * Dh;

    for (int t = 0; t < nt; t++) {
        const int k0 = t * 64;
        // Cooperative load of K/V tiles (64x64 each), float4, coalesced.
#pragma unroll
        for (int it = 0; it < 4; it++) {
            int idx = tid + it * 256;          // 0..1023
            int r   = idx >> 4;                // 0..63
            int c   = (idx & 15) * 4;          // 0..60
            const float* kp = Kbase + (size_t)(k0 + r) * HD + c;
            const float* vp = Vbase + (size_t)(k0 + r) * HD + c;
            *(float4*)&Ks[r][c] = *(const float4*)kp;
            *(float4*)&Vs[r][c] = *(const float4*)vp;
        }
        __syncthreads();

        // Scores for all 64 keys of this tile (replicated across the 4 lanes
        // of each query row via xor-shuffle reduction over head dims).
        float s[64];
#pragma unroll
        for (int k = 0; k < 64; k++) {
            float p = 0.f;
#pragma unroll
            for (int j = 0; j < 16; j += 4) {
                float4 kv = *(const float4*)&Ks[k][d0 + j];
                p = fmaf(qreg[j + 0], kv.x, p);
                p = fmaf(qreg[j + 1], kv.y, p);
                p = fmaf(qreg[j + 2], kv.z, p);
                p = fmaf(qreg[j + 3], kv.w, p);
            }
            p += __shfl_xor_sync(0xffffffffu, p, 1);
            p += __shfl_xor_sync(0xffffffffu, p, 2);
            s[k] = (k0 + k < L) ? p * 0.125f : -1e30f;
        }

        // Online softmax update
        float mt = m;
#pragma unroll
        for (int k = 0; k < 64; k++) mt = fmaxf(mt, s[k]);
        float scale = __expf(m - mt);
        float ls = 0.f;
#pragma unroll
        for (int k = 0; k < 64; k++) {
            s[k] = __expf(s[k] - mt);
            ls += s[k];
        }
#pragma unroll
        for (int j = 0; j < 16; j++) acc[j] *= scale;

        // acc += P @ V for this thread's 16 dims
#pragma unroll
        for (int k = 0; k < 64; k++) {
            const float pk = s[k];
#pragma unroll
            for (int j = 0; j < 16; j += 4) {
                float4 v = *(const float4*)&Vs[k][d0 + j];
                acc[j + 0] = fmaf(pk, v.x, acc[j + 0]);
                acc[j + 1] = fmaf(pk, v.y, acc[j + 1]);
                acc[j + 2] = fmaf(pk, v.z, acc[j + 2]);
                acc[j + 3] = fmaf(pk, v.w, acc[j + 3]);
            }
        }
        l = l * scale + ls;
        m = mt;
        __syncthreads();
    }

    const float inv = (qg < L && l > 0.f) ? (1.0f / l) : 0.f;
    float* aop = g_AO + ((size_t)(b * Sseq + qg)) * HD + h * Dh + d0;
#pragma unroll
    for (int j = 0; j < 16; j += 4) {
        float4 o;
        o.x = acc[j + 0] * inv;
        o.y = acc[j + 1] * inv;
        o.z = acc[j + 2] * inv;
        o.w = acc[j + 3] * inv;
        *(float4*)(aop + j) = o;
    }
}

// ---------------------------------------------------------------------------
extern "C" void kernel_launch(void* const* d_in, const int* in_sizes, int n_in,
                              void* d_out, int out_size)
{
    const float* x      = (const float*)d_in[0];
    const int*   length = (const int*)d_in[1];
    const float* Wq     = (const float*)d_in[2];
    const float* Wk     = (const float*)d_in[3];
    const float* Wv     = (const float*)d_in[4];
    const float* Wx     = (const float*)d_in[5];
    float*       out    = (float*)d_out;

    (void)in_sizes; (void)n_in; (void)out_size;

    // QKV projections: [8192,512] @ [512,512] x3 (z dim selects weight)
    qkv_kernel<<<dim3(HD / 128, MROWS / 128, 3), 256>>>(x, Wq, Wk, Wv);

    // Attention: one CTA per (q-tile, head, batch)
    attn_kernel<<<dim3(Sseq / 64, Hn, Bsz), 256>>>(length);

    // Output projection: [8192,512] @ [512,512]
    out_kernel<<<dim3(Cin / 128, MROWS / 128), 256>>>(Wx, out);
}

// round 2
// speedup vs baseline: 2.8669x; 2.8669x over previous
#include <cuda_runtime.h>
#include <math.h>

// Problem constants (fixed shapes)
#define Bsz   4
#define Sseq  2048
#define Cin   512
#define Hn    8
#define Dh    64
#define HD    512            // Hn * Dh
#define MROWS (Bsz * Sseq)   // 8192

// Scratch buffers (allocation-free rule: __device__ globals)
__device__ float g_Q[MROWS * HD];
__device__ float g_K[MROWS * HD];
__device__ float g_V[MROWS * HD];
__device__ float g_AO[MROWS * HD];

// ---------------------------------------------------------------------------
// 128x128 tiled fp32 GEMM: C[M,N] = A[M,K] @ B[K,N], row-major.
// ---------------------------------------------------------------------------
__device__ __forceinline__ void gemm128x128(const float* __restrict__ A,
                                            const float* __restrict__ Bm,
                                            float* __restrict__ C,
                                            int K, int N)
{
    __shared__ float As[8][128];   // transposed A tile: As[k][m]
    __shared__ float Bs[8][132];   // padded

    const int tid  = threadIdx.x;
    const int row0 = blockIdx.y * 128;
    const int col0 = blockIdx.x * 128;
    const int tx   = tid & 15;     // N direction
    const int ty   = tid >> 4;     // M direction

    const int arow = tid >> 1;            // 0..127
    const int acol = (tid & 1) * 4;       // 0 or 4
    const int brow = tid >> 5;            // 0..7
    const int bcol = (tid & 31) * 4;      // 0..124

    float acc[8][8];
#pragma unroll
    for (int i = 0; i < 8; i++)
#pragma unroll
        for (int j = 0; j < 8; j++) acc[i][j] = 0.f;

    const float* Aptr = A + (size_t)(row0 + arow) * K + acol;
    const float* Bptr = Bm + (size_t)brow * N + col0 + bcol;

    for (int k0 = 0; k0 < K; k0 += 8) {
        float4 av = *(const float4*)(Aptr + k0);
        float4 bv = *(const float4*)(Bptr + (size_t)k0 * N);

        As[acol + 0][arow] = av.x;
        As[acol + 1][arow] = av.y;
        As[acol + 2][arow] = av.z;
        As[acol + 3][arow] = av.w;
        *(float4*)&Bs[brow][bcol] = bv;
        __syncthreads();

#pragma unroll
        for (int kk = 0; kk < 8; kk++) {
            float a[8], b[8];
            *(float4*)&a[0] = *(const float4*)&As[kk][ty * 8];
            *(float4*)&a[4] = *(const float4*)&As[kk][ty * 8 + 4];
            *(float4*)&b[0] = *(const float4*)&Bs[kk][tx * 8];
            *(float4*)&b[4] = *(const float4*)&Bs[kk][tx * 8 + 4];
#pragma unroll
            for (int i = 0; i < 8; i++)
#pragma unroll
                for (int j = 0; j < 8; j++)
                    acc[i][j] = fmaf(a[i], b[j], acc[i][j]);
        }
        __syncthreads();
    }

#pragma unroll
    for (int i = 0; i < 8; i++) {
        float* cp = C + (size_t)(row0 + ty * 8 + i) * N + col0 + tx * 8;
        float4 o0, o1;
        o0.x = acc[i][0]; o0.y = acc[i][1]; o0.z = acc[i][2]; o0.w = acc[i][3];
        o1.x = acc[i][4]; o1.y = acc[i][5]; o1.z = acc[i][6]; o1.w = acc[i][7];
        *(float4*)cp       = o0;
        *(float4*)(cp + 4) = o1;
    }
}

__global__ __launch_bounds__(256) void qkv_kernel(const float* __restrict__ x,
                                                  const float* __restrict__ Wq,
                                                  const float* __restrict__ Wk,
                                                  const float* __restrict__ Wv)
{
    const float* W = (blockIdx.z == 0) ? Wq : (blockIdx.z == 1) ? Wk : Wv;
    float* Cout    = (blockIdx.z == 0) ? g_Q : (blockIdx.z == 1) ? g_K : g_V;
    gemm128x128(x, W, Cout, Cin, HD);
}

__global__ __launch_bounds__(256) void out_kernel(const float* __restrict__ Wx,
                                                  float* __restrict__ out)
{
    gemm128x128(g_AO, Wx, out, HD, Cin);
}

// ---------------------------------------------------------------------------
// Flash-style attention v2: GEMM-structured, 64q x 64k tiles, D=64.
// 256 threads. Phase1: S = Q@K^T (4x4 reg tiles, float4 smem reads from
// transposed Q/K). Phase2: online softmax (4 threads/row, 16 exp each).
// Phase3: O += P@V (4x4 reg tiles, float4 reads of transposed P and V).
// ---------------------------------------------------------------------------
#define QT_OFF   0                    // Qt[d][i]  pitch 68
#define KT_OFF   (64 * 68)            // Kt[d][j]  pitch 68
#define VS_OFF   (2 * 64 * 68)        // Vs[j][d]  pitch 68
#define PT_OFF   (3 * 64 * 68)        // Pt[j][i]  pitch 68
#define SCL_OFF  (4 * 64 * 68)        // scl[64]
#define LRW_OFF  (4 * 64 * 68 + 64)   // lrow[64]
#define ATTN_SMEM_FLOATS (4 * 64 * 68 + 128)
#define ATTN_SMEM_BYTES  (ATTN_SMEM_FLOATS * 4)

__global__ __launch_bounds__(256, 2) void attn_kernel(const int* __restrict__ length)
{
    extern __shared__ float sm[];
    float* Qt   = sm + QT_OFF;
    float* Kt   = sm + KT_OFF;
    float* Vs   = sm + VS_OFF;
    float* Pt   = sm + PT_OFF;
    float* scl  = sm + SCL_OFF;
    float* lrow = sm + LRW_OFF;

    const int b  = blockIdx.z;
    const int h  = blockIdx.y;
    const int q0 = blockIdx.x * 64;
    const int L  = length[b];

    const int tid = threadIdx.x;
    const int tx  = tid & 15;
    const int ty  = tid >> 4;
    const int iq0 = tx * 4;   // phase1: query group
    const int jk0 = ty * 4;   // phase1: key group
    const int i0  = ty * 4;   // phase3: query rows
    const int d0  = tx * 4;   // phase3: head dims
    const int si  = tid >> 2; // phase2: softmax row
    const int sub = tid & 3;  // phase2: sub-lane

    // Load Q tile transposed: Qt[d][i]. 4 threads per row, conflict-free-ish.
    {
        const int r  = tid & 63;
        const int c0 = (tid >> 6) * 4;
        const float* qp = g_Q + ((size_t)(b * Sseq + q0 + r)) * HD + h * Dh;
#pragma unroll
        for (int cc = 0; cc < 64; cc += 16) {
            float4 v = *(const float4*)(qp + c0 + cc);
            Qt[(c0 + cc + 0) * 68 + r] = v.x;
            Qt[(c0 + cc + 1) * 68 + r] = v.y;
            Qt[(c0 + cc + 2) * 68 + r] = v.z;
            Qt[(c0 + cc + 3) * 68 + r] = v.w;
        }
    }

    float oacc[4][4];
#pragma unroll
    for (int i = 0; i < 4; i++)
#pragma unroll
        for (int j = 0; j < 4; j++) oacc[i][j] = 0.f;
    float mrow = -1e30f, lacc = 0.f;

    const float* Kbase = g_K + ((size_t)b * Sseq) * HD + h * Dh;
    const float* Vbase = g_V + ((size_t)b * Sseq) * HD + h * Dh;

    const int nt = (L + 63) >> 6;
    for (int t = 0; t < nt; t++) {
        const int k0 = t * 64;

        // Load K transposed: Kt[d][j]
        {
            const int r  = tid & 63;
            const int c0 = (tid >> 6) * 4;
            const float* kp = Kbase + (size_t)(k0 + r) * HD;
#pragma unroll
            for (int cc = 0; cc < 64; cc += 16) {
                float4 v = *(const float4*)(kp + c0 + cc);
                Kt[(c0 + cc + 0) * 68 + r] = v.x;
                Kt[(c0 + cc + 1) * 68 + r] = v.y;
                Kt[(c0 + cc + 2) * 68 + r] = v.z;
                Kt[(c0 + cc + 3) * 68 + r] = v.w;
            }
        }
        // Load V row-major (coalesced): Vs[j][d]
#pragma unroll
        for (int it = 0; it < 4; it++) {
            int idx = tid + it * 256;
            int r   = idx >> 4;
            int c   = (idx & 15) * 4;
            float4 v = *(const float4*)(Vbase + (size_t)(k0 + r) * HD + c);
            *(float4*)&Vs[r * 68 + c] = v;
        }
        __syncthreads();

        // Phase 1: S[iq0..+3][jk0..+3] = Q@K^T, masked+scaled, store transposed
        {
            float sacc[4][4];
#pragma unroll
            for (int i = 0; i < 4; i++)
#pragma unroll
                for (int j = 0; j < 4; j++) sacc[i][j] = 0.f;

#pragma unroll 8
            for (int d = 0; d < 64; d++) {
                float4 qa = *(const float4*)&Qt[d * 68 + iq0];
                float4 kb = *(const float4*)&Kt[d * 68 + jk0];
                sacc[0][0] = fmaf(qa.x, kb.x, sacc[0][0]);
                sacc[0][1] = fmaf(qa.x, kb.y, sacc[0][1]);
                sacc[0][2] = fmaf(qa.x, kb.z, sacc[0][2]);
                sacc[0][3] = fmaf(qa.x, kb.w, sacc[0][3]);
                sacc[1][0] = fmaf(qa.y, kb.x, sacc[1][0]);
                sacc[1][1] = fmaf(qa.y, kb.y, sacc[1][1]);
                sacc[1][2] = fmaf(qa.y, kb.z, sacc[1][2]);
                sacc[1][3] = fmaf(qa.y, kb.w, sacc[1][3]);
                sacc[2][0] = fmaf(qa.z, kb.x, sacc[2][0]);
                sacc[2][1] = fmaf(qa.z, kb.y, sacc[2][1]);
                sacc[2][2] = fmaf(qa.z, kb.z, sacc[2][2]);
                sacc[2][3] = fmaf(qa.z, kb.w, sacc[2][3]);
                sacc[3][0] = fmaf(qa.w, kb.x, sacc[3][0]);
                sacc[3][1] = fmaf(qa.w, kb.y, sacc[3][1]);
                sacc[3][2] = fmaf(qa.w, kb.z, sacc[3][2]);
                sacc[3][3] = fmaf(qa.w, kb.w, sacc[3][3]);
            }
#pragma unroll
            for (int jj = 0; jj < 4; jj++) {
                const int jg = k0 + jk0 + jj;
                const bool valid = (jg < L);
#pragma unroll
                for (int ii = 0; ii < 4; ii++) {
                    float v = sacc[ii][jj] * 0.125f;
                    Pt[(jk0 + jj) * 68 + iq0 + ii] = valid ? v : -1e30f;
                }
            }
        }
        __syncthreads();

        // Phase 2: online softmax over this tile's 64 keys (4 threads/row)
        {
            float vals[16];
            float mloc = -1e30f;
#pragma unroll
            for (int c = 0; c < 16; c++) {
                vals[c] = Pt[(sub * 16 + c) * 68 + si];
                mloc = fmaxf(mloc, vals[c]);
            }
            mloc = fmaxf(mloc, __shfl_xor_sync(0xffffffffu, mloc, 1));
            mloc = fmaxf(mloc, __shfl_xor_sync(0xffffffffu, mloc, 2));
            float mnew = fmaxf(mrow, mloc);
            float sc   = __expf(mrow - mnew);
            float ls   = 0.f;
#pragma unroll
            for (int c = 0; c < 16; c++) {
                float e = __expf(vals[c] - mnew);
                Pt[(sub * 16 + c) * 68 + si] = e;
                ls += e;
            }
            ls += __shfl_xor_sync(0xffffffffu, ls, 1);
            ls += __shfl_xor_sync(0xffffffffu, ls, 2);
            lacc = lacc * sc + ls;
            mrow = mnew;
            if (sub == 0) { scl[si] = sc; lrow[si] = lacc; }
        }
        __syncthreads();

        // Phase 3: O[i0..+3][d0..+3] = O*scale + P@V
        {
#pragma unroll
            for (int ii = 0; ii < 4; ii++) {
                float s = scl[i0 + ii];
#pragma unroll
                for (int dd = 0; dd < 4; dd++) oacc[ii][dd] *= s;
            }
#pragma unroll 8
            for (int j = 0; j < 64; j++) {
                float4 vv = *(const float4*)&Vs[j * 68 + d0];
                float4 pp = *(const float4*)&Pt[j * 68 + i0];
                oacc[0][0] = fmaf(pp.x, vv.x, oacc[0][0]);
                oacc[0][1] = fmaf(pp.x, vv.y, oacc[0][1]);
                oacc[0][2] = fmaf(pp.x, vv.z, oacc[0][2]);
                oacc[0][3] = fmaf(pp.x, vv.w, oacc[0][3]);
                oacc[1][0] = fmaf(pp.y, vv.x, oacc[1][0]);
                oacc[1][1] = fmaf(pp.y, vv.y, oacc[1][1]);
                oacc[1][2] = fmaf(pp.y, vv.z, oacc[1][2]);
                oacc[1][3] = fmaf(pp.y, vv.w, oacc[1][3]);
                oacc[2][0] = fmaf(pp.z, vv.x, oacc[2][0]);
                oacc[2][1] = fmaf(pp.z, vv.y, oacc[2][1]);
                oacc[2][2] = fmaf(pp.z, vv.z, oacc[2][2]);
                oacc[2][3] = fmaf(pp.z, vv.w, oacc[2][3]);
                oacc[3][0] = fmaf(pp.w, vv.x, oacc[3][0]);
                oacc[3][1] = fmaf(pp.w, vv.y, oacc[3][1]);
                oacc[3][2] = fmaf(pp.w, vv.z, oacc[3][2]);
                oacc[3][3] = fmaf(pp.w, vv.w, oacc[3][3]);
            }
        }
        __syncthreads();
    }

    // Epilogue: normalize and write
#pragma unroll
    for (int ii = 0; ii < 4; ii++) {
        const int i  = i0 + ii;
        const int qg = q0 + i;
        const float l  = lrow[i];
        const float inv = (qg < L && l > 0.f) ? (1.0f / l) : 0.f;
        float4 o;
        o.x = oacc[ii][0] * inv;
        o.y = oacc[ii][1] * inv;
        o.z = oacc[ii][2] * inv;
        o.w = oacc[ii][3] * inv;
        *(float4*)(g_AO + ((size_t)(b * Sseq + qg)) * HD + h * Dh + d0) = o;
    }
}

// ---------------------------------------------------------------------------
extern "C" void kernel_launch(void* const* d_in, const int* in_sizes, int n_in,
                              void* d_out, int out_size)
{
    const float* x      = (const float*)d_in[0];
    const int*   length = (const int*)d_in[1];
    const float* Wq     = (const float*)d_in[2];
    const float* Wk     = (const float*)d_in[3];
    const float* Wv     = (const float*)d_in[4];
    const float* Wx     = (const float*)d_in[5];
    float*       out    = (float*)d_out;

    (void)in_sizes; (void)n_in; (void)out_size;

    static bool attr_set = false;
    if (!attr_set) {
        cudaFuncSetAttribute(attn_kernel,
                             cudaFuncAttributeMaxDynamicSharedMemorySize,
                             ATTN_SMEM_BYTES);
        attr_set = true;
    }

    qkv_kernel<<<dim3(HD / 128, MROWS / 128, 3), 256>>>(x, Wq, Wk, Wv);
    attn_kernel<<<dim3(Sseq / 64, Hn, Bsz), 256, ATTN_SMEM_BYTES>>>(length);
    out_kernel<<<dim3(Cin / 128, MROWS / 128), 256>>>(Wx, out);
}